// round 6
// baseline (speedup 1.0000x reference)
#include <cuda_runtime.h>
#include <math.h>

#define FULL_MASK 0xffffffffu
#define TWO_PI_F 6.28318530717958647692f

// ---------------- packed f32x2 primitives ----------------
typedef unsigned long long f2;   // two packed fp32 lanes: {lo, hi}

__device__ __forceinline__ f2 f2pack(float a, float b) {
    f2 r; asm("mov.b64 %0, {%1, %2};" : "=l"(r) : "f"(a), "f"(b)); return r;
}
__device__ __forceinline__ void f2unpack(f2 v, float& a, float& b) {
    asm("mov.b64 {%0, %1}, %2;" : "=f"(a), "=f"(b) : "l"(v));
}
__device__ __forceinline__ f2 f2add(f2 a, f2 b) {
    f2 r; asm("add.rn.f32x2 %0, %1, %2;" : "=l"(r) : "l"(a), "l"(b)); return r;
}
__device__ __forceinline__ f2 f2mul(f2 a, f2 b) {
    f2 r; asm("mul.rn.f32x2 %0, %1, %2;" : "=l"(r) : "l"(a), "l"(b)); return r;
}
__device__ __forceinline__ f2 f2fma(f2 a, f2 b, f2 c) {
    f2 r; asm("fma.rn.f32x2 %0, %1, %2, %3;" : "=l"(r) : "l"(a), "l"(b), "l"(c)); return r;
}
__device__ __forceinline__ f2 f2splat(float s) { return f2pack(s, s); }

__device__ __forceinline__ f2 f2shfl_xor(f2 v, int m) {
    float a, b; f2unpack(v, a, b);
    a = __shfl_xor_sync(FULL_MASK, a, m);
    b = __shfl_xor_sync(FULL_MASK, b, m);
    return f2pack(a, b);
}

__device__ __forceinline__ constexpr int brev4c(int p) {
    return ((p & 1) << 3) | ((p & 2) << 1) | ((p & 4) >> 1) | ((p & 8) >> 3);
}

// four-step twiddle table: g_tw512[p*32+lane] = w512^{lane * brev4(p)}
__device__ float2 g_tw512[16 * 32];

__global__ void init_tw_kernel() {
    int e = threadIdx.x;            // 0..511
    int p  = e >> 5;
    int ln = e & 31;
    int k1 = brev4c(p);
    float ang = -(TWO_PI_F / 512.f) * (float)(ln * k1);
    float s, c;
    sincosf(ang, &s, &c);
    g_tw512[p * 32 + ln] = make_float2(c, s);
}

// Per-thread 16-point DIF FFT over 16 register slots (packed: 2 FFTs at once).
// Input slot s = time index; output slot p = bin brev4(p). Compile-time twiddles.
__device__ __forceinline__ void fft16_regs(f2 (&xr)[16], f2 (&xi)[16], f2 NEG)
{
    const float C1 = 0.9238795325f, C2 = 0.7071067812f, C3 = 0.3826834324f;
    {   // span 8, twiddles w16^j
        const float WR[8] = {1.f,  C1,  C2,  C3, 0.f, -C3, -C2, -C1};
        const float WI[8] = {0.f, -C3, -C2, -C1, -1.f, -C1, -C2, -C3};
        #pragma unroll
        for (int j = 0; j < 8; ++j) {
            f2 ur = f2add(xr[j], xr[j+8]),        ui = f2add(xi[j], xi[j+8]);
            f2 vr = f2fma(xr[j+8], NEG, xr[j]),   vi = f2fma(xi[j+8], NEG, xi[j]);
            xr[j] = ur; xi[j] = ui;
            if (j == 0)      { xr[j+8] = vr;  xi[j+8] = vi; }
            else if (j == 4) { xr[j+8] = vi;  xi[j+8] = f2mul(vr, NEG); }     // * -i
            else {
                f2 wr = f2splat(WR[j]), wi = f2splat(WI[j]);
                f2 t1 = f2mul(vi, wi);
                xr[j+8] = f2fma(t1, NEG, f2mul(vr, wr));
                xi[j+8] = f2fma(vi, wr, f2mul(vr, wi));
            }
        }
    }
    {   // span 4, twiddles w8^j
        const float WR[4] = {1.f,  C2, 0.f, -C2};
        const float WI[4] = {0.f, -C2, -1.f, -C2};
        #pragma unroll
        for (int b = 0; b < 16; b += 8)
        #pragma unroll
        for (int j = 0; j < 4; ++j) {
            int p = b + j, q = p + 4;
            f2 ur = f2add(xr[p], xr[q]),        ui = f2add(xi[p], xi[q]);
            f2 vr = f2fma(xr[q], NEG, xr[p]),   vi = f2fma(xi[q], NEG, xi[p]);
            xr[p] = ur; xi[p] = ui;
            if (j == 0)      { xr[q] = vr; xi[q] = vi; }
            else if (j == 2) { xr[q] = vi; xi[q] = f2mul(vr, NEG); }          // * -i
            else {
                f2 wr = f2splat(WR[j]), wi = f2splat(WI[j]);
                f2 t1 = f2mul(vi, wi);
                xr[q] = f2fma(t1, NEG, f2mul(vr, wr));
                xi[q] = f2fma(vi, wr, f2mul(vr, wi));
            }
        }
    }
    // span 2, twiddles {1, -i}
    #pragma unroll
    for (int b = 0; b < 16; b += 4) {
        {
            int p = b, q = b + 2;
            f2 ur = f2add(xr[p], xr[q]),      ui = f2add(xi[p], xi[q]);
            f2 vr = f2fma(xr[q], NEG, xr[p]), vi = f2fma(xi[q], NEG, xi[p]);
            xr[p] = ur; xi[p] = ui; xr[q] = vr; xi[q] = vi;
        }
        {
            int p = b + 1, q = b + 3;
            f2 ur = f2add(xr[p], xr[q]),      ui = f2add(xi[p], xi[q]);
            f2 vr = f2fma(xr[q], NEG, xr[p]), vi = f2fma(xi[q], NEG, xi[p]);
            xr[p] = ur; xi[p] = ui;
            xr[q] = vi; xi[q] = f2mul(vr, NEG);   // * -i
        }
    }
    // span 1
    #pragma unroll
    for (int b = 0; b < 16; b += 2) {
        f2 ur = f2add(xr[b], xr[b+1]),      ui = f2add(xi[b], xi[b+1]);
        f2 vr = f2fma(xr[b+1], NEG, xr[b]), vi = f2fma(xi[b+1], NEG, xi[b]);
        xr[b] = ur; xi[b] = ui; xr[b+1] = vr; xi[b+1] = vi;
    }
}

// w32^s tables (s in [0,16)): w = exp(-2*pi*i*s/32)
__device__ __constant__ const float W32R_[16] = {
    1.f, 0.98078528f, 0.92387953f, 0.83146961f, 0.70710678f, 0.55557023f,
    0.38268343f, 0.19509032f, 0.f, -0.19509032f, -0.38268343f, -0.55557023f,
    -0.70710678f, -0.83146961f, -0.92387953f, -0.98078528f };
__device__ __constant__ const float W32I_[16] = {
    0.f, -0.19509032f, -0.38268343f, -0.55557023f, -0.70710678f, -0.83146961f,
    -0.92387953f, -0.98078528f, -1.f, -0.98078528f, -0.92387953f, -0.83146961f,
    -0.70710678f, -0.55557023f, -0.38268343f, -0.19509032f };

// Full 512-point packed FFT. Output: slot p on lane (=16*par+k1) holds the
// NATURAL frequency bin k = lane + 32*brev4(p).
// Derivation: n = 32*n1 + m. Pass1 FFT16 over n1 + w512^{m k1} twiddle gives
// y_{k1}[m]; need B[k2]=FFT32_m. Split m = n2 + 16*n3 (DIF): even k2 from
// e=y[n2]+y[n2+16], odd k2 from o=(y[n2]-y[n2+16])*w32^{n2}; FFT16 over n2
// gives k2 = 2*brev4(p) + par, so k = k1 + 16*k2 = lane + 32*brev4(p).
__device__ __forceinline__ void fft512B(f2 (&xr)[16], f2 (&xi)[16],
                                        int lane, int par, f2* __restrict__ slab,
                                        f2 NEG, f2 SP)
{
    // pass 1: FFT16 over slots (n1)
    fft16_regs(xr, xi, NEG);

    // four-step twiddle: slot p *= w512^{lane * brev4(p)}  (global table, L1-cached)
    #pragma unroll
    for (int p = 1; p < 16; ++p) {
        float2 w = __ldg(&g_tw512[p * 32 + lane]);
        f2 wr = f2splat(w.x), wi = f2splat(w.y);
        f2 t1 = f2mul(xi[p], wi);
        f2 ni = f2fma(xi[p], wr, f2mul(xr[p], wi));
        xr[p] = f2fma(t1, NEG, f2mul(xr[p], wr));
        xi[p] = ni;
    }

    const int k1r = lane & 15;
    const int wb  = k1r * 33;           // pad-33: reads are pair-broadcast + conflict-free

    // transpose through the slab, folding the n3 radix-2 into the read
    f2 nxr[16];
    __syncwarp();
    #pragma unroll
    for (int p = 0; p < 16; ++p)
        slab[brev4c(p) * 33 + lane] = xr[p];
    __syncwarp();
    #pragma unroll
    for (int s = 0; s < 16; ++s) {
        f2 y0 = slab[wb + s];
        f2 y1 = slab[wb + s + 16];
        nxr[s] = f2fma(y1, SP, y0);     // e = y0+y1 (par=0) | y0-y1 (par=1)
    }
    __syncwarp();
    #pragma unroll
    for (int p = 0; p < 16; ++p)
        slab[brev4c(p) * 33 + lane] = xi[p];
    __syncwarp();
    #pragma unroll
    for (int s = 0; s < 16; ++s) {
        f2 y0 = slab[wb + s];
        f2 y1 = slab[wb + s + 16];
        xi[s] = f2fma(y1, SP, y0);
    }
    #pragma unroll
    for (int s = 0; s < 16; ++s) xr[s] = nxr[s];

    // odd-branch pre-twiddle: par=1 lanes multiply by w32^{n2}; par=0 by 1 (FSEL)
    #pragma unroll
    for (int s = 1; s < 16; ++s) {
        float cr = par ? W32R_[s] : 1.f;
        float ci = par ? W32I_[s] : 0.f;
        f2 wr = f2splat(cr), wi = f2splat(ci);
        f2 t1 = f2mul(xi[s], wi);
        f2 ni = f2fma(xi[s], wr, f2mul(xr[s], wi));
        xr[s] = f2fma(t1, NEG, f2mul(xr[s], wr));
        xi[s] = ni;
    }

    // pass 2: FFT16 over n2 -> k2 = 2*brev4(slot) + par
    fft16_regs(xr, xi, NEG);
}

// out[b] = Im( sum_f Z[f]^2 conj(T[f]) ) / (2D), Z=FFT(h+ir), T=FFT(t).
// Quad scheme: per 4 rows (a,b,c,d): 3 packed FFTs instead of 4 —
//   FFT(z_a|z_b), FFT(z_c|z_d), FFT(t_a+i t_b | t_c+i t_d).
// T spectra stored UNPACKED to smem by pair and natural k. For Z phase zp,
// BOTH packed rows read spectrum pair zp (this routing was R5's bug):
//   row even: out = Im(sum Z^2 c0)/(4D),  c0 = conj(Tc[k]) + Tc[-k]
//   row odd:  out = Re(sum Z^2 c1)/(4D),  c1 = conj(Tc[k]) - Tc[-k]
__global__ void __launch_bounds__(128, 4)
hole_kernel(const float* __restrict__ h, const float* __restrict__ r,
            const float* __restrict__ t, float* __restrict__ out, int nrows)
{
    const int lane = threadIdx.x & 31;
    const int wid  = threadIdx.x >> 5;
    const int warp = blockIdx.x * 4 + wid;
    const int nw   = gridDim.x * 4;
    const int par  = lane >> 4;

    __shared__ f2   slab_s[4][16 * 33];     // 4.2 KB/warp transpose scratch
    __shared__ float tre_s[4][2][512];      // 4 KB/warp: Re Tc per pair, natural k
    __shared__ float tim_s[4][2][512];      // 4 KB/warp: Im Tc per pair
    f2* __restrict__ slab = slab_s[wid];

    const f2 NEG = f2splat(-1.f);
    const f2 SP  = f2splat(par ? -1.f : 1.f);

    for (int base = warp; base < nrows; base += 4 * nw) {
        int rw[4];
        #pragma unroll
        for (int j = 0; j < 4; ++j) {
            int rj = base + j * nw;
            rw[j] = (rj < nrows) ? rj : base;
        }

        // ================= T phase: packed FFT(t_a + i t_b | t_c + i t_d) ========
        {
            const float* ta = t + (size_t)rw[0] * 512 + lane;
            const float* tb = t + (size_t)rw[1] * 512 + lane;
            const float* tc = t + (size_t)rw[2] * 512 + lane;
            const float* td = t + (size_t)rw[3] * 512 + lane;
            f2 xr[16], xi[16];
            #pragma unroll
            for (int s = 0; s < 16; ++s) {
                xr[s] = f2pack(ta[32 * s], tc[32 * s]);
                xi[s] = f2pack(tb[32 * s], td[32 * s]);
            }
            fft512B(xr, xi, lane, par, slab, NEG, SP);

            // store spectra unpacked, indexed by natural k (WAR-safe: all lanes
            // passed through fft512B's syncwarps after last quad's reads)
            __syncwarp();
            #pragma unroll
            for (int p = 0; p < 16; ++p) {
                int k = lane + 32 * brev4c(p);
                float relo, rehi, imlo, imhi;
                f2unpack(xr[p], relo, rehi);
                f2unpack(xi[p], imlo, imhi);
                tre_s[wid][0][k] = relo;    // pair (a,b)
                tre_s[wid][1][k] = rehi;    // pair (c,d)
                tim_s[wid][0][k] = imlo;
                tim_s[wid][1][k] = imhi;
            }
            __syncwarp();
        }

        // ================= Z phases: zp=0 -> rows (a,b), zp=1 -> rows (c,d) ======
        #pragma unroll 1
        for (int zp = 0; zp < 2; ++zp) {
            int r0 = rw[2 * zp], r1 = rw[2 * zp + 1];
            const float* h0 = h + (size_t)r0 * 512 + lane;
            const float* h1 = h + (size_t)r1 * 512 + lane;
            const float* rr0 = r + (size_t)r0 * 512 + lane;
            const float* rr1 = r + (size_t)r1 * 512 + lane;

            f2 xr[16], xi[16];
            #pragma unroll
            for (int s = 0; s < 16; ++s) {
                xr[s] = f2pack(h0[32 * s], h1[32 * s]);
                xi[s] = f2pack(rr0[32 * s], rr1[32 * s]);
            }
            fft512B(xr, xi, lane, par, slab, NEG, SP);   // (Z0[k] | Z1[k])

            const float* trez = tre_s[wid][zp];    // BOTH rows use pair zp
            const float* timz = tim_s[wid][zp];

            // lo accumulates Im(Z0^2 c0); hi accumulates Re(Z1^2 c1)
            f2 acc = f2splat(0.f);
            #pragma unroll
            for (int p = 0; p < 16; ++p) {
                int ka = lane + 32 * brev4c(p);
                int km = (512 - ka) & 511;
                float tcr = trez[ka], tci = timz[ka];
                float tmr = trez[km], tmi = timz[km];

                float c0i = tmi - tci;     // Im c0
                float c0r = tcr + tmr;     // Re c0
                float c1r = tcr - tmr;     // Re c1
                float nc1i = tci + tmi;    // -Im c1

                f2 X = f2pack(c0i, c1r);
                f2 Y = f2pack(c0r, nc1i);

                f2 a2 = f2mul(xr[p], xr[p]);
                f2 b2 = f2mul(xi[p], xi[p]);
                f2 Wr = f2fma(b2, NEG, a2);        // Re Z^2
                f2 Wi = f2mul(xr[p], xi[p]);       // (1/2) Im Z^2

                acc = f2fma(Wr, X, acc);           // + ReZ2*c0i   | + ReZ2*c1r
                Y = f2add(Y, Y);
                acc = f2fma(Wi, Y, acc);           // + ImZ2*c0r   | - ImZ2*c1i
            }

            // packed warp reduction tree
            #pragma unroll
            for (int o = 16; o; o >>= 1)
                acc = f2add(acc, f2shfl_xor(acc, o));

            if (lane == 0) {
                float oa, ob;
                f2unpack(acc, oa, ob);
                int j0 = 2 * zp, j1 = 2 * zp + 1;
                if (base + j0 * nw < nrows) out[base + j0 * nw] = oa * (1.f / 2048.f);
                if (base + j1 * nw < nrows) out[base + j1 * nw] = ob * (1.f / 2048.f);
            }
        }
    }
}

extern "C" void kernel_launch(void* const* d_in, const int* in_sizes, int n_in,
                              void* d_out, int out_size)
{
    const float* h = (const float*)d_in[0];
    const float* r = (const float*)d_in[1];
    const float* t = (const float*)d_in[2];
    float* out = (float*)d_out;

    int nrows = in_sizes[0] / 512;      // 131072

    init_tw_kernel<<<1, 512>>>();       // idempotent, graph-capturable
    hole_kernel<<<4096, 128>>>(h, r, t, out, nrows);   // 16384 warps -> 2 quads/warp
}

// round 7
// speedup vs baseline: 1.1370x; 1.1370x over previous
#include <cuda_runtime.h>
#include <math.h>

#define FULL_MASK 0xffffffffu
#define TWO_PI_F 6.28318530717958647692f

// ---------------- packed f32x2 primitives ----------------
typedef unsigned long long f2;   // two packed fp32 lanes: {lo, hi}

__device__ __forceinline__ f2 f2pack(float a, float b) {
    f2 r; asm("mov.b64 %0, {%1, %2};" : "=l"(r) : "f"(a), "f"(b)); return r;
}
__device__ __forceinline__ void f2unpack(f2 v, float& a, float& b) {
    asm("mov.b64 {%0, %1}, %2;" : "=f"(a), "=f"(b) : "l"(v));
}
__device__ __forceinline__ f2 f2add(f2 a, f2 b) {
    f2 r; asm("add.rn.f32x2 %0, %1, %2;" : "=l"(r) : "l"(a), "l"(b)); return r;
}
__device__ __forceinline__ f2 f2mul(f2 a, f2 b) {
    f2 r; asm("mul.rn.f32x2 %0, %1, %2;" : "=l"(r) : "l"(a), "l"(b)); return r;
}
__device__ __forceinline__ f2 f2fma(f2 a, f2 b, f2 c) {
    f2 r; asm("fma.rn.f32x2 %0, %1, %2, %3;" : "=l"(r) : "l"(a), "l"(b), "l"(c)); return r;
}
__device__ __forceinline__ f2 f2splat(float s) { return f2pack(s, s); }

__device__ __forceinline__ f2 f2shfl_xor(f2 v, int m) {
    float a, b; f2unpack(v, a, b);
    a = __shfl_xor_sync(FULL_MASK, a, m);
    b = __shfl_xor_sync(FULL_MASK, b, m);
    return f2pack(a, b);
}

__device__ __forceinline__ constexpr int brev4c(int p) {
    return ((p & 1) << 3) | ((p & 2) << 1) | ((p & 4) >> 1) | ((p & 8) >> 3);
}

// four-step twiddle table: g_tw512[p*32+lane] = w512^{lane * brev4(p)}
__device__ float2 g_tw512[16 * 32];

__global__ void init_tw_kernel() {
    int e = threadIdx.x;            // 0..511
    int p  = e >> 5;
    int ln = e & 31;
    int k1 = brev4c(p);
    float ang = -(TWO_PI_F / 512.f) * (float)(ln * k1);
    float s, c;
    sincosf(ang, &s, &c);
    g_tw512[p * 32 + ln] = make_float2(c, s);
}

// Per-thread 16-point DIF FFT over 16 register slots (packed: 2 FFTs at once).
// Input slot s = time index; output slot p = bin brev4(p). Compile-time twiddles.
__device__ __forceinline__ void fft16_regs(f2 (&xr)[16], f2 (&xi)[16], f2 NEG)
{
    const float C1 = 0.9238795325f, C2 = 0.7071067812f, C3 = 0.3826834324f;
    {   // span 8, twiddles w16^j
        const float WR[8] = {1.f,  C1,  C2,  C3, 0.f, -C3, -C2, -C1};
        const float WI[8] = {0.f, -C3, -C2, -C1, -1.f, -C1, -C2, -C3};
        #pragma unroll
        for (int j = 0; j < 8; ++j) {
            f2 ur = f2add(xr[j], xr[j+8]),        ui = f2add(xi[j], xi[j+8]);
            f2 vr = f2fma(xr[j+8], NEG, xr[j]),   vi = f2fma(xi[j+8], NEG, xi[j]);
            xr[j] = ur; xi[j] = ui;
            if (j == 0)      { xr[j+8] = vr;  xi[j+8] = vi; }
            else if (j == 4) { xr[j+8] = vi;  xi[j+8] = f2mul(vr, NEG); }     // * -i
            else {
                f2 wr = f2splat(WR[j]), wi = f2splat(WI[j]);
                f2 t1 = f2mul(vi, wi);
                xr[j+8] = f2fma(t1, NEG, f2mul(vr, wr));
                xi[j+8] = f2fma(vi, wr, f2mul(vr, wi));
            }
        }
    }
    {   // span 4, twiddles w8^j
        const float WR[4] = {1.f,  C2, 0.f, -C2};
        const float WI[4] = {0.f, -C2, -1.f, -C2};
        #pragma unroll
        for (int b = 0; b < 16; b += 8)
        #pragma unroll
        for (int j = 0; j < 4; ++j) {
            int p = b + j, q = p + 4;
            f2 ur = f2add(xr[p], xr[q]),        ui = f2add(xi[p], xi[q]);
            f2 vr = f2fma(xr[q], NEG, xr[p]),   vi = f2fma(xi[q], NEG, xi[p]);
            xr[p] = ur; xi[p] = ui;
            if (j == 0)      { xr[q] = vr; xi[q] = vi; }
            else if (j == 2) { xr[q] = vi; xi[q] = f2mul(vr, NEG); }          // * -i
            else {
                f2 wr = f2splat(WR[j]), wi = f2splat(WI[j]);
                f2 t1 = f2mul(vi, wi);
                xr[q] = f2fma(t1, NEG, f2mul(vr, wr));
                xi[q] = f2fma(vi, wr, f2mul(vr, wi));
            }
        }
    }
    // span 2, twiddles {1, -i}
    #pragma unroll
    for (int b = 0; b < 16; b += 4) {
        {
            int p = b, q = b + 2;
            f2 ur = f2add(xr[p], xr[q]),      ui = f2add(xi[p], xi[q]);
            f2 vr = f2fma(xr[q], NEG, xr[p]), vi = f2fma(xi[q], NEG, xi[p]);
            xr[p] = ur; xi[p] = ui; xr[q] = vr; xi[q] = vi;
        }
        {
            int p = b + 1, q = b + 3;
            f2 ur = f2add(xr[p], xr[q]),      ui = f2add(xi[p], xi[q]);
            f2 vr = f2fma(xr[q], NEG, xr[p]), vi = f2fma(xi[q], NEG, xi[p]);
            xr[p] = ur; xi[p] = ui;
            xr[q] = vi; xi[q] = f2mul(vr, NEG);   // * -i
        }
    }
    // span 1
    #pragma unroll
    for (int b = 0; b < 16; b += 2) {
        f2 ur = f2add(xr[b], xr[b+1]),      ui = f2add(xi[b], xi[b+1]);
        f2 vr = f2fma(xr[b+1], NEG, xr[b]), vi = f2fma(xi[b+1], NEG, xi[b]);
        xr[b] = ur; xi[b] = ui; xr[b+1] = vr; xi[b+1] = vi;
    }
}

// w32^s tables (s in [0,16)): w = exp(-2*pi*i*s/32)
__device__ __constant__ const float W32R_[16] = {
    1.f, 0.98078528f, 0.92387953f, 0.83146961f, 0.70710678f, 0.55557023f,
    0.38268343f, 0.19509032f, 0.f, -0.19509032f, -0.38268343f, -0.55557023f,
    -0.70710678f, -0.83146961f, -0.92387953f, -0.98078528f };
__device__ __constant__ const float W32I_[16] = {
    0.f, -0.19509032f, -0.38268343f, -0.55557023f, -0.70710678f, -0.83146961f,
    -0.92387953f, -0.98078528f, -1.f, -0.98078528f, -0.92387953f, -0.83146961f,
    -0.70710678f, -0.55557023f, -0.38268343f, -0.19509032f };

// Full 512-point packed FFT (two independent FFTs in f2 lanes).
// Output: slot p on lane (=16*par+k1) holds bin k = lane + 32*brev4(p)
// (order only needs to be consistent — the reduction sums all bins).
// Single-round float4 slab transpose with the n3 radix-2 folded into the read:
//   even k2 (par=0 lanes): e = y[n2] + y[n2+16]
//   odd  k2 (par=1 lanes): o = (y[n2] - y[n2+16]) * w32^{n2}
// then FFT16 over n2.
__device__ __forceinline__ void fft512C(f2 (&xr)[16], f2 (&xi)[16],
                                        int lane, int par,
                                        ulonglong2* __restrict__ slab,
                                        f2 NEG, f2 SP)
{
    // pass 1: FFT16 over slots (n1)
    fft16_regs(xr, xi, NEG);

    // four-step twiddle: slot p *= w512^{lane * brev4(p)} (global table, L1-resident)
    #pragma unroll
    for (int p = 1; p < 16; ++p) {
        float2 w = __ldg(&g_tw512[p * 32 + lane]);
        f2 wr = f2splat(w.x), wi = f2splat(w.y);
        f2 t1 = f2mul(xi[p], wi);
        f2 ni = f2fma(xi[p], wr, f2mul(xr[p], wi));
        xr[p] = f2fma(t1, NEG, f2mul(xr[p], wr));
        xi[p] = ni;
    }

    const int wb = (lane & 15) * 33;    // read row base (pad-33 float4 rows)

    // single-round transpose: {xr,xi} as one 16B element
    __syncwarp();
    #pragma unroll
    for (int p = 0; p < 16; ++p)
        slab[brev4c(p) * 33 + lane] = make_ulonglong2(xr[p], xi[p]);
    __syncwarp();
    #pragma unroll
    for (int s = 0; s < 16; ++s) {
        ulonglong2 y0 = slab[wb + s];
        ulonglong2 y1 = slab[wb + s + 16];
        xr[s] = f2fma((f2)y1.x, SP, (f2)y0.x);   // e (par=0) | y0-y1 (par=1)
        xi[s] = f2fma((f2)y1.y, SP, (f2)y0.y);
    }

    // odd-branch pre-twiddle: par=1 lanes multiply by w32^{n2}; par=0 by 1 (FSEL)
    #pragma unroll
    for (int s = 1; s < 16; ++s) {
        float cr = par ? W32R_[s] : 1.f;
        float ci = par ? W32I_[s] : 0.f;
        f2 wr = f2splat(cr), wi = f2splat(ci);
        f2 t1 = f2mul(xi[s], wi);
        f2 ni = f2fma(xi[s], wr, f2mul(xr[s], wi));
        xr[s] = f2fma(t1, NEG, f2mul(xr[s], wr));
        xi[s] = ni;
    }

    // pass 2: FFT16 over n2 -> k2 = 2*brev4(slot) + par
    fft16_regs(xr, xi, NEG);
}

// out[b] = Im( sum_f Z[f]^2 * conj(T[f]) ) / (2*D), Z = FFT(h+ir), T = FFT(t).
// Packed per row: lo = Z-FFT, hi = T-FFT. Independent rows -> full pipelining.
__global__ void __launch_bounds__(128, 4)
hole_kernel(const float* __restrict__ h, const float* __restrict__ r,
            const float* __restrict__ t, float* __restrict__ out, int nrows)
{
    const int lane = threadIdx.x & 31;
    const int wid  = threadIdx.x >> 5;
    const int warp = blockIdx.x * 4 + wid;
    const int nw   = gridDim.x * 4;
    const int par  = lane >> 4;

    __shared__ ulonglong2 slab_s[4][16 * 33];   // 8.25 KB/warp float4 slab
    ulonglong2* __restrict__ slab = slab_s[wid];

    const f2 NEG = f2splat(-1.f);
    const f2 SP  = f2splat(par ? -1.f : 1.f);

    for (int row = warp; row < nrows; row += nw) {
        size_t base = (size_t)row * 512 + (size_t)lane;
        const float* hp = h + base;
        const float* rp = r + base;
        const float* tp = t + base;

        // coalesced loads; lo = Z input (h + i r), hi = T input (t + i 0)
        f2 xr[16], xi[16];
        #pragma unroll
        for (int s = 0; s < 16; ++s) {
            float hv = hp[32 * s];
            float tv = tp[32 * s];
            float rv = rp[32 * s];
            xr[s] = f2pack(hv, tv);
            xi[s] = f2pack(rv, 0.f);
        }

        fft512C(xr, xi, lane, par, slab, NEG, SP);

        // acc = sum over this lane's 16 bins of Im(Z^2 * conj(T))
        float acc = 0.f;
        #pragma unroll
        for (int s = 0; s < 16; ++s) {
            float a, tr, b, ti;
            f2unpack(xr[s], a, tr);    // lo = Re Z, hi = Re T
            f2unpack(xi[s], b, ti);    // lo = Im Z, hi = Im T
            float im2 = 2.f * a * b;               // Im(Z^2)
            float re2 = a * a - b * b;             // Re(Z^2)
            acc = fmaf(im2, tr, acc);
            acc = fmaf(-re2, ti, acc);
        }
        #pragma unroll
        for (int o = 16; o; o >>= 1)
            acc += __shfl_xor_sync(FULL_MASK, acc, o);

        if (lane == 0) out[row] = acc * (1.f / 1024.f);   // 1/(2*D)
    }
}

extern "C" void kernel_launch(void* const* d_in, const int* in_sizes, int n_in,
                              void* d_out, int out_size)
{
    const float* h = (const float*)d_in[0];
    const float* r = (const float*)d_in[1];
    const float* t = (const float*)d_in[2];
    float* out = (float*)d_out;

    int nrows = in_sizes[0] / 512;      // 131072

    init_tw_kernel<<<1, 512>>>();       // idempotent, graph-capturable
    hole_kernel<<<4096, 128>>>(h, r, t, out, nrows);   // 16384 warps -> 8 rows/warp
}